// round 16
// baseline (speedup 1.0000x reference)
#include <cuda_runtime.h>
#include <cuda_bf16.h>
#include <math_constants.h>
#include <cstdint>

// Problem constants
#define BATCH 8
#define CIN   512
#define NPIX  4096          // 64*64
#define OCQKV 1536          // 3 * INNER
#define INNER 512
#define HEADS 8
#define DH    64
#define INV_N (1.0f/4096.0f)

// GEMM1 tiling: CTA 128x128, BK=32, bf16 m16n8k16, 4-stage cp.async ring
#define BM 128
#define BN 128
#define BK 32
#define AS2 40              // A smem row stride (bf16)
#define BS2 136             // B smem row stride (bf16)
#define STAGES 4
#define A_STAGE (BM * AS2)  // 5120 elems
#define B_STAGE (BK * BS2)  // 4352 elems
#define GEMM_SMEM_BYTES (STAGES * (A_STAGE + B_STAGE) * 2)   // 75776
#define APPLY_SMEM_BYTES (DH * 256 * 2 + DH * DH * 4)        // 49152

// Fused proj+LN tiling: CTA 512x64 (full channel dim), 512 threads
#define FBM 512
#define FBN 64
#define FAS 40              // A row stride (k-major)
#define FBS2 40             // B row stride: 32 k + 8 pad (mid is [n][k] now)
#define FA_STAGE (FBM * FAS)    // 20480 elems
#define FB_STAGE2 (FBN * FBS2)  // 2560 elems
#define FUSED_SMEM_BYTES (STAGES * (FA_STAGE + FB_STAGE2) * 2)  // 184320

// Scratch (allocation-free: __device__ globals)
__device__ __align__(16) __nv_bfloat16 g_qkvb[(size_t)BATCH * OCQKV * NPIX]; // 96 MB
__device__ __align__(16) float g_ctx [(size_t)BATCH * HEADS * DH * DH];       // 1 MB
__device__ __align__(16) __nv_bfloat16 g_xb  [(size_t)BATCH * CIN * NPIX];    // 32 MB
// mid stored PIXEL-MAJOR: [b][pix][ch] -> apply stores coalesced, fused reads [n][k]
__device__ __align__(16) __nv_bfloat16 g_midb[(size_t)BATCH * NPIX * INNER];  // 32 MB
__device__ __align__(16) __nv_bfloat16 g_wqkvb[(size_t)OCQKV * CIN];          // 1.5 MB [M,K]
__device__ __align__(16) __nv_bfloat16 g_woutb[(size_t)INNER * INNER];        // 0.5 MB [M,K]

// ---------------------------------------------------------------------------
__device__ __forceinline__ void cp_async16(void* smem, const void* gmem) {
    uint32_t s = (uint32_t)__cvta_generic_to_shared(smem);
    asm volatile("cp.async.cg.shared.global [%0], [%1], 16;" :: "r"(s), "l"(gmem));
}

__device__ __forceinline__ uint32_t smem_u32(const void* p) {
    return (uint32_t)__cvta_generic_to_shared(p);
}

__device__ __forceinline__ void ldmx4(uint32_t* r, uint32_t addr) {
    asm volatile("ldmatrix.sync.aligned.m8n8.x4.shared.b16 {%0,%1,%2,%3}, [%4];"
                 : "=r"(r[0]), "=r"(r[1]), "=r"(r[2]), "=r"(r[3]) : "r"(addr));
}

__device__ __forceinline__ void ldmx4_trans(uint32_t* r, uint32_t addr) {
    asm volatile("ldmatrix.sync.aligned.m8n8.x4.trans.shared.b16 {%0,%1,%2,%3}, [%4];"
                 : "=r"(r[0]), "=r"(r[1]), "=r"(r[2]), "=r"(r[3]) : "r"(addr));
}

__device__ __forceinline__ void mma_bf16(float* c, const uint32_t* a, const uint32_t* b) {
    asm volatile(
        "mma.sync.aligned.m16n8k16.row.col.f32.bf16.bf16.f32 "
        "{%0,%1,%2,%3}, {%4,%5,%6,%7}, {%8,%9}, {%0,%1,%2,%3};\n"
        : "+f"(c[0]), "+f"(c[1]), "+f"(c[2]), "+f"(c[3])
        : "r"(a[0]), "r"(a[1]), "r"(a[2]), "r"(a[3]), "r"(b[0]), "r"(b[1]));
}

// ---------------------------------------------------------------------------
// fp32 -> bf16 convert (vectorized x4)
// ---------------------------------------------------------------------------
__global__ __launch_bounds__(256) void cvt_bf16_kernel(
    const float* __restrict__ in, __nv_bfloat16* __restrict__ out, int n)
{
    int i = (blockIdx.x * 256 + threadIdx.x) * 4;
    if (i < n) {
        float4 v = *reinterpret_cast<const float4*>(in + i);
        __nv_bfloat162 lo = __floats2bfloat162_rn(v.x, v.y);
        __nv_bfloat162 hi = __floats2bfloat162_rn(v.z, v.w);
        uint2 pk;
        pk.x = *reinterpret_cast<uint32_t*>(&lo);
        pk.y = *reinterpret_cast<uint32_t*>(&hi);
        *reinterpret_cast<uint2*>(out + i) = pk;
    }
}

// ---------------------------------------------------------------------------
// GEMM1: 4-stage pipelined bf16, bf16 out. CTA 128x128 (8 warps 4Mx2N).
// 3 CTAs/SM (launch_bounds cap ~80 regs; 3x74KB smem fits 228KB).
// ---------------------------------------------------------------------------
__global__ __launch_bounds__(256, 3) void gemm_bf16_pipe(
    const __nv_bfloat16* __restrict__ A,   // [M,K]
    const __nv_bfloat16* __restrict__ Xg,  // [BATCH][K][N]
    __nv_bfloat16* __restrict__ Yg,        // [BATCH][M][N]
    int M, int K, int Nn)
{
    extern __shared__ __nv_bfloat16 smb[];
    __nv_bfloat16* Asm = smb;
    __nv_bfloat16* Bsm = smb + STAGES * A_STAGE;

    const int b  = blockIdx.z;
    const __nv_bfloat16* X = Xg + (size_t)b * K * Nn;
    __nv_bfloat16* Y = Yg + (size_t)b * M * Nn;
    const int m0 = blockIdx.y * BM;
    const int n0 = blockIdx.x * BN;
    const int tid  = threadIdx.x;
    const int lane = tid & 31;
    const int warp = tid >> 5;
    const int wm = (warp & 3) * 32;
    const int wn = (warp >> 2) * 64;
    const int r = lane >> 2;
    const int c = lane & 3;

    const int NIT = K >> 5;

    float acc[2][8][4];
#pragma unroll
    for (int mt = 0; mt < 2; mt++)
#pragma unroll
        for (int nt = 0; nt < 8; nt++)
#pragma unroll
            for (int i = 0; i < 4; i++) acc[mt][nt][i] = 0.f;

    auto load_stage = [&](int s, int k0) {
        const __nv_bfloat16* a_src = A + (size_t)m0 * K + k0;
        const __nv_bfloat16* b_src = X + (size_t)k0 * Nn + n0;
        __nv_bfloat16* Ad = Asm + s * A_STAGE;
        __nv_bfloat16* Bd = Bsm + s * B_STAGE;
#pragma unroll
        for (int u = 0; u < 2; u++) {
            int idx = tid + u * 256;
            int m  = idx >> 2, ga = idx & 3;
            cp_async16(&Ad[m * AS2 + ga * 8], a_src + (size_t)m * K + ga * 8);
            int kk = idx >> 4, gb = idx & 15;
            cp_async16(&Bd[kk * BS2 + gb * 8], b_src + (size_t)kk * Nn + gb * 8);
        }
    };

    const int lane15 = lane & 15;
    const int khalf  = (lane >> 4) << 3;
    const uint32_t a_base = smem_u32(Asm) + (uint32_t)((wm + lane15) * AS2 + khalf) * 2;
    const uint32_t b_base = smem_u32(Bsm) + (uint32_t)(lane15 * BS2 + wn + khalf) * 2;

    load_stage(0, 0);       asm volatile("cp.async.commit_group;");
    load_stage(1, BK);      asm volatile("cp.async.commit_group;");
    load_stage(2, 2 * BK);  asm volatile("cp.async.commit_group;");

    for (int it = 0; it < NIT; it++) {
        asm volatile("cp.async.wait_group 2;");
        __syncthreads();

        if (it + 3 < NIT)
            load_stage((it + 3) & 3, (it + 3) * BK);
        asm volatile("cp.async.commit_group;");

        const uint32_t aoff = a_base + (uint32_t)((it & 3) * A_STAGE) * 2;
        const uint32_t boff = b_base + (uint32_t)((it & 3) * B_STAGE) * 2;

#pragma unroll
        for (int ks = 0; ks < 2; ks++) {
            const int kc = ks * 16;
            uint32_t af[2][4];
            ldmx4(af[0], aoff + kc * 2);
            ldmx4(af[1], aoff + (16 * AS2 + kc) * 2);
#pragma unroll
            for (int j = 0; j < 4; j++) {
                uint32_t bf[4];
                ldmx4_trans(bf, boff + (kc * BS2 + j * 16) * 2);
                mma_bf16(acc[0][2 * j],     af[0], bf);
                mma_bf16(acc[0][2 * j + 1], af[0], bf + 2);
                mma_bf16(acc[1][2 * j],     af[1], bf);
                mma_bf16(acc[1][2 * j + 1], af[1], bf + 2);
            }
        }
    }

#pragma unroll
    for (int mt = 0; mt < 2; mt++) {
        const int mrow = m0 + wm + mt * 16 + r;
#pragma unroll
        for (int nt = 0; nt < 8; nt++) {
            const int ncol = n0 + wn + nt * 8 + 2 * c;
            __nv_bfloat162 o0 = __floats2bfloat162_rn(acc[mt][nt][0], acc[mt][nt][1]);
            __nv_bfloat162 o1 = __floats2bfloat162_rn(acc[mt][nt][2], acc[mt][nt][3]);
            *reinterpret_cast<__nv_bfloat162*>(&Y[(size_t)mrow * Nn + ncol]) = o0;
            *reinterpret_cast<__nv_bfloat162*>(&Y[(size_t)(mrow + 8) * Nn + ncol]) = o1;
        }
    }
}

// ---------------------------------------------------------------------------
// FUSED proj GEMM + channel LayerNorm.
// CTA 512(M) x 64(N px), 512 threads / 16 warps along M, warp tile 32x64.
// mid is PIXEL-MAJOR [b][n][k]: B tile rows = pixels, ldmatrix NON-trans
// (lane -> n-row; regs r0/r2 = n-lo k-lo/hi, r1/r3 = n-hi k-lo/hi).
// ---------------------------------------------------------------------------
__global__ __launch_bounds__(512, 1) void fused_proj_ln(
    const __nv_bfloat16* __restrict__ A,   // [512, 512] bf16 [M,K]
    const __nv_bfloat16* __restrict__ Mg,  // [BATCH][NPIX][512] bf16 (pixel-major)
    float* __restrict__ out,               // [BATCH][512][NPIX]
    const float* __restrict__ bias)
{
    extern __shared__ __nv_bfloat16 smb[];
    __nv_bfloat16* Asm = smb;                          // [STAGES][512][FAS]
    __nv_bfloat16* Bsm = smb + STAGES * FA_STAGE;      // [STAGES][FBN][FBS2]

    const int b  = blockIdx.z;
    const __nv_bfloat16* X = Mg + (size_t)b * NPIX * INNER;
    const int n0 = blockIdx.x * FBN;
    const int tid  = threadIdx.x;
    const int lane = tid & 31;
    const int warp = tid >> 5;          // 0..15
    const int wm = warp * 32;
    const int r = lane >> 2;            // 0..7
    const int c = lane & 3;             // 0..3

    const int NIT = INNER >> 5;         // 16

    float acc[2][8][4];
#pragma unroll
    for (int mt = 0; mt < 2; mt++)
#pragma unroll
        for (int nt = 0; nt < 8; nt++)
#pragma unroll
            for (int i = 0; i < 4; i++) acc[mt][nt][i] = 0.f;

    auto load_stage = [&](int s, int k0) {
        const __nv_bfloat16* a_src = A + k0;
        const __nv_bfloat16* b_src = X + (size_t)n0 * INNER + k0;
        __nv_bfloat16* Ad = Asm + s * FA_STAGE;
        __nv_bfloat16* Bd = Bsm + s * FB_STAGE2;
#pragma unroll
        for (int u = 0; u < 4; u++) {
            int idx = tid + u * 512;          // 2048 chunks: 512 rows x 4
            int m  = idx >> 2, ga = idx & 3;
            cp_async16(&Ad[m * FAS + ga * 8], a_src + (size_t)m * INNER + ga * 8);
        }
        if (tid < 256) {                      // 256 chunks: 64 n-rows x 4
            int row = tid >> 2, gb = tid & 3;
            cp_async16(&Bd[row * FBS2 + gb * 8], b_src + (size_t)row * INNER + gb * 8);
        }
    };

    const int lane15 = lane & 15;
    const int khalf  = (lane >> 4) << 3;
    const uint32_t a_base = smem_u32(Asm) + (uint32_t)((wm + lane15) * FAS + khalf) * 2;
    const uint32_t b_base = smem_u32(Bsm) + (uint32_t)(lane15 * FBS2 + khalf) * 2;

    load_stage(0, 0);       asm volatile("cp.async.commit_group;");
    load_stage(1, BK);      asm volatile("cp.async.commit_group;");
    load_stage(2, 2 * BK);  asm volatile("cp.async.commit_group;");

    for (int it = 0; it < NIT; it++) {
        asm volatile("cp.async.wait_group 2;");
        __syncthreads();

        if (it + 3 < NIT)
            load_stage((it + 3) & 3, (it + 3) * BK);
        asm volatile("cp.async.commit_group;");

        const uint32_t aoff = a_base + (uint32_t)((it & 3) * FA_STAGE) * 2;
        const uint32_t boff = b_base + (uint32_t)((it & 3) * FB_STAGE2) * 2;

#pragma unroll
        for (int ks = 0; ks < 2; ks++) {
            const int kc = ks * 16;
            uint32_t af[2][4];
            ldmx4(af[0], aoff + kc * 2);
            ldmx4(af[1], aoff + (16 * FAS + kc) * 2);
#pragma unroll
            for (int j = 0; j < 4; j++) {
                uint32_t bq[4];
                ldmx4(bq, boff + (j * 16 * FBS2 + kc) * 2);
                uint32_t blo[2] = { bq[0], bq[2] };   // n-lo (rows j*16+0..7)
                uint32_t bhi[2] = { bq[1], bq[3] };   // n-hi (rows j*16+8..15)
                mma_bf16(acc[0][2 * j],     af[0], blo);
                mma_bf16(acc[0][2 * j + 1], af[0], bhi);
                mma_bf16(acc[1][2 * j],     af[1], blo);
                mma_bf16(acc[1][2 * j + 1], af[1], bhi);
            }
        }
    }

    asm volatile("cp.async.wait_group 0;");
    __syncthreads();   // stage smem dead; reuse for LN stats below

    // --- bias ---
#pragma unroll
    for (int mt = 0; mt < 2; mt++) {
        const float bv0 = bias[wm + mt * 16 + r];
        const float bv1 = bias[wm + mt * 16 + r + 8];
#pragma unroll
        for (int nt = 0; nt < 8; nt++) {
            acc[mt][nt][0] += bv0; acc[mt][nt][1] += bv0;
            acc[mt][nt][2] += bv1; acc[mt][nt][3] += bv1;
        }
    }

    // --- per-column partial sums ---
    float se[8], so[8], qe[8], qo[8];
#pragma unroll
    for (int nt = 0; nt < 8; nt++) {
        se[nt] = acc[0][nt][0] + acc[0][nt][2] + acc[1][nt][0] + acc[1][nt][2];
        so[nt] = acc[0][nt][1] + acc[0][nt][3] + acc[1][nt][1] + acc[1][nt][3];
        qe[nt] = acc[0][nt][0]*acc[0][nt][0] + acc[0][nt][2]*acc[0][nt][2]
               + acc[1][nt][0]*acc[1][nt][0] + acc[1][nt][2]*acc[1][nt][2];
        qo[nt] = acc[0][nt][1]*acc[0][nt][1] + acc[0][nt][3]*acc[0][nt][3]
               + acc[1][nt][1]*acc[1][nt][1] + acc[1][nt][3]*acc[1][nt][3];
    }
#pragma unroll
    for (int off = 4; off <= 16; off <<= 1) {
#pragma unroll
        for (int nt = 0; nt < 8; nt++) {
            se[nt] += __shfl_xor_sync(0xffffffff, se[nt], off);
            so[nt] += __shfl_xor_sync(0xffffffff, so[nt], off);
            qe[nt] += __shfl_xor_sync(0xffffffff, qe[nt], off);
            qo[nt] += __shfl_xor_sync(0xffffffff, qo[nt], off);
        }
    }

    float* ssum  = reinterpret_cast<float*>(smb);            // [16][64]
    float* ssum2 = ssum + 16 * 64;                           // [16][64]
    float* smu   = ssum2 + 16 * 64;                          // [64]
    float* srs   = smu + 64;                                 // [64]

    if (lane < 4) {
#pragma unroll
        for (int nt = 0; nt < 8; nt++) {
            ssum [warp * 64 + nt * 8 + 2 * lane]     = se[nt];
            ssum [warp * 64 + nt * 8 + 2 * lane + 1] = so[nt];
            ssum2[warp * 64 + nt * 8 + 2 * lane]     = qe[nt];
            ssum2[warp * 64 + nt * 8 + 2 * lane + 1] = qo[nt];
        }
    }
    __syncthreads();

    if (tid < 64) {
        float ts = 0.f, ts2 = 0.f;
#pragma unroll
        for (int w = 0; w < 16; w++) {
            ts  += ssum [w * 64 + tid];
            ts2 += ssum2[w * 64 + tid];
        }
        const float mu  = ts * (1.f / 512.f);
        const float var = ts2 * (1.f / 512.f) - mu * mu;
        smu[tid] = mu;
        srs[tid] = rsqrtf(var + 1e-5f);
    }
    __syncthreads();

    // --- normalize + store ---
    float* ob = out + (size_t)b * INNER * NPIX;
#pragma unroll
    for (int nt = 0; nt < 8; nt++) {
        const int col = nt * 8 + 2 * c;
        const float mu0 = smu[col],     rs0 = srs[col];
        const float mu1 = smu[col + 1], rs1 = srs[col + 1];
#pragma unroll
        for (int mt = 0; mt < 2; mt++) {
            const int mrow = wm + mt * 16 + r;
            float2 o0, o1;
            o0.x = (acc[mt][nt][0] - mu0) * rs0;
            o0.y = (acc[mt][nt][1] - mu1) * rs1;
            o1.x = (acc[mt][nt][2] - mu0) * rs0;
            o1.y = (acc[mt][nt][3] - mu1) * rs1;
            *reinterpret_cast<float2*>(&ob[(size_t)mrow * NPIX + n0 + col]) = o0;
            *reinterpret_cast<float2*>(&ob[(size_t)(mrow + 8) * NPIX + n0 + col]) = o1;
        }
    }
}

// ---------------------------------------------------------------------------
// softmax over N (4096 bf16 contiguous) for the k block. One block per row.
// ---------------------------------------------------------------------------
__global__ __launch_bounds__(256) void softmax_k_kernel()
{
    const int row = blockIdx.x;
    const int b   = row >> 9;
    const int ch  = row & 511;
    __nv_bfloat16* base = g_qkvb + ((size_t)b * OCQKV + INNER + ch) * NPIX;
    const int tid = threadIdx.x;
    const int lane = tid & 31, wid = tid >> 5;

    __shared__ float red[8];
    __shared__ float bcast;

    uint32_t w[8];
    *reinterpret_cast<uint4*>(w)     = *reinterpret_cast<const uint4*>(base + tid * 16);
    *reinterpret_cast<uint4*>(w + 4) = *reinterpret_cast<const uint4*>(base + tid * 16 + 8);
    float vals[16];
#pragma unroll
    for (int i = 0; i < 8; i++) {
        float2 f = __bfloat1622float2(*reinterpret_cast<__nv_bfloat162*>(&w[i]));
        vals[2 * i] = f.x; vals[2 * i + 1] = f.y;
    }

    float m = vals[0];
#pragma unroll
    for (int j = 1; j < 16; j++) m = fmaxf(m, vals[j]);
#pragma unroll
    for (int off = 16; off > 0; off >>= 1)
        m = fmaxf(m, __shfl_xor_sync(0xffffffff, m, off));
    if (lane == 0) red[wid] = m;
    __syncthreads();
    if (tid == 0) {
        float mm = red[0];
#pragma unroll
        for (int w2 = 1; w2 < 8; w2++) mm = fmaxf(mm, red[w2]);
        bcast = mm;
    }
    __syncthreads();
    const float mx = bcast;

    float s = 0.f;
#pragma unroll
    for (int j = 0; j < 16; j++) { vals[j] = __expf(vals[j] - mx); s += vals[j]; }
#pragma unroll
    for (int off = 16; off > 0; off >>= 1)
        s += __shfl_xor_sync(0xffffffff, s, off);
    if (lane == 0) red[wid] = s;
    __syncthreads();
    if (tid == 0) {
        float ss = 0.f;
#pragma unroll
        for (int w2 = 0; w2 < 8; w2++) ss += red[w2];
        bcast = 1.f / ss;
    }
    __syncthreads();
    const float inv = bcast;
#pragma unroll
    for (int i = 0; i < 8; i++) {
        __nv_bfloat162 o = __floats2bfloat162_rn(vals[2 * i] * inv, vals[2 * i + 1] * inv);
        w[i] = *reinterpret_cast<uint32_t*>(&o);
    }
    *reinterpret_cast<uint4*>(base + tid * 16)     = *reinterpret_cast<uint4*>(w);
    *reinterpret_cast<uint4*>(base + tid * 16 + 8) = *reinterpret_cast<uint4*>(w + 4);
}

__global__ __launch_bounds__(256) void zero_ctx_kernel()
{
    int i = blockIdx.x * 256 + threadIdx.x;
    if (i < BATCH * HEADS * DH * DH) g_ctx[i] = 0.f;
}

// ---------------------------------------------------------------------------
// context[b,h,d,e] += sum_{n in chunk} k_sm[d,n] * (v[e,n]/N)   (bf16 reads)
// ---------------------------------------------------------------------------
__global__ __launch_bounds__(256) void context_kernel()
{
    const int nchunk = blockIdx.x;
    const int h = blockIdx.y;
    const int b = blockIdx.z;
    const __nv_bfloat16* kbase = g_qkvb + ((size_t)b * OCQKV + INNER     + h * DH) * NPIX;
    const __nv_bfloat16* vbase = g_qkvb + ((size_t)b * OCQKV + 2 * INNER + h * DH) * NPIX;

    __shared__ float Ks[64][65];
    __shared__ float Vs[64][65];

    const int tid = threadIdx.x;
    const int ty = tid >> 4, tx = tid & 15;
    float acc[4][4];
#pragma unroll
    for (int i = 0; i < 4; i++)
#pragma unroll
        for (int j = 0; j < 4; j++) acc[i][j] = 0.f;

    for (int nt = 0; nt < 8; nt++) {
        const int n0 = nchunk * 512 + nt * 64;
#pragma unroll
        for (int it = 0; it < 2; it++) {
            int idx = tid + it * 256;
            int r  = idx >> 3;
            int c8 = (idx & 7) * 8;
            uint4 kv = *reinterpret_cast<const uint4*>(&kbase[(size_t)r * NPIX + n0 + c8]);
            uint4 vv = *reinterpret_cast<const uint4*>(&vbase[(size_t)r * NPIX + n0 + c8]);
            const uint32_t* kw = reinterpret_cast<const uint32_t*>(&kv);
            const uint32_t* vw = reinterpret_cast<const uint32_t*>(&vv);
#pragma unroll
            for (int q = 0; q < 4; q++) {
                float2 kf = __bfloat1622float2(*reinterpret_cast<const __nv_bfloat162*>(&kw[q]));
                float2 vf = __bfloat1622float2(*reinterpret_cast<const __nv_bfloat162*>(&vw[q]));
                Ks[c8 + 2 * q][r]     = kf.x;
                Ks[c8 + 2 * q + 1][r] = kf.y;
                Vs[c8 + 2 * q][r]     = vf.x * INV_N;
                Vs[c8 + 2 * q + 1][r] = vf.y * INV_N;
            }
        }
        __syncthreads();
#pragma unroll
        for (int nn = 0; nn < 64; nn++) {
            float kr[4], vr[4];
#pragma unroll
            for (int i = 0; i < 4; i++) kr[i] = Ks[nn][ty * 4 + i];
#pragma unroll
            for (int j = 0; j < 4; j++) vr[j] = Vs[nn][tx * 4 + j];
#pragma unroll
            for (int i = 0; i < 4; i++)
#pragma unroll
                for (int j = 0; j < 4; j++) acc[i][j] += kr[i] * vr[j];
        }
        __syncthreads();
    }
    float* cbase = g_ctx + (size_t)(b * HEADS + h) * DH * DH;
#pragma unroll
    for (int i = 0; i < 4; i++)
#pragma unroll
        for (int j = 0; j < 4; j++)
            atomicAdd(&cbase[(ty * 4 + i) * DH + tx * 4 + j], acc[i][j]);
}

// ---------------------------------------------------------------------------
// Fused softmax_q + apply, q tile staged in smem (single global read).
// Writes g_midb PIXEL-MAJOR: [b][n][h*64+e] -> 8x uint4 contiguous per thread.
// ---------------------------------------------------------------------------
__global__ __launch_bounds__(256) void apply_kernel()
{
    extern __shared__ char ap_sm[];
    __nv_bfloat16* sq = reinterpret_cast<__nv_bfloat16*>(ap_sm);      // [64][256]
    float* ctxs = reinterpret_cast<float*>(ap_sm + DH * 256 * 2);     // [64][64]

    const int n0 = blockIdx.x * 256;
    const int h = blockIdx.y;
    const int b = blockIdx.z;
    const int tid = threadIdx.x;

    const float* csrc = g_ctx + (size_t)(b * HEADS + h) * DH * DH;
    for (int i = tid; i < DH * DH; i += 256)
        ctxs[i] = csrc[i];

    const __nv_bfloat16* qb = g_qkvb + ((size_t)b * OCQKV + h * DH) * NPIX + n0;
#pragma unroll
    for (int u = 0; u < 8; u++) {
        int idx = tid + u * 256;
        int d  = idx >> 5;
        int c8 = (idx & 31) * 8;
        *reinterpret_cast<uint4*>(&sq[d * 256 + c8]) =
            *reinterpret_cast<const uint4*>(qb + (size_t)d * NPIX + c8);
    }
    __syncthreads();

    const int p = tid;
    float mx = -CUDART_INF_F;
#pragma unroll 8
    for (int d = 0; d < 64; d++)
        mx = fmaxf(mx, __bfloat162float(sq[d * 256 + p]));
    float s = 0.f;
#pragma unroll 8
    for (int d = 0; d < 64; d++)
        s += __expf(__bfloat162float(sq[d * 256 + p]) - mx);
    const float inv = 1.f / (s * 8.f);

    float acc[64];
#pragma unroll
    for (int e = 0; e < 64; e++) acc[e] = 0.f;
#pragma unroll 4
    for (int d = 0; d < 64; d++) {
        float qd = __expf(__bfloat162float(sq[d * 256 + p]) - mx) * inv;
        const float* cr = &ctxs[d * 64];
#pragma unroll
        for (int e = 0; e < 64; e++) acc[e] += cr[e] * qd;
    }
    // pixel-major coalesced store: 64 contiguous bf16 per thread
    __nv_bfloat16* obase = g_midb + ((size_t)b * NPIX + n0 + p) * INNER + h * DH;
#pragma unroll
    for (int e = 0; e < 64; e += 8) {
        uint4 pk;
        uint32_t* pw = reinterpret_cast<uint32_t*>(&pk);
#pragma unroll
        for (int q = 0; q < 4; q++) {
            __nv_bfloat162 o = __floats2bfloat162_rn(acc[e + 2 * q], acc[e + 2 * q + 1]);
            pw[q] = *reinterpret_cast<uint32_t*>(&o);
        }
        *reinterpret_cast<uint4*>(obase + e) = pk;
    }
}

// ---------------------------------------------------------------------------
extern "C" void kernel_launch(void* const* d_in, const int* in_sizes, int n_in,
                              void* d_out, int out_size)
{
    (void)in_sizes; (void)n_in; (void)out_size;
    const float* x     = (const float*)d_in[0];   // [8,512,64,64]
    const float* w_qkv = (const float*)d_in[1];   // [1536,512]
    const float* w_out = (const float*)d_in[2];   // [512,512]
    const float* b_out = (const float*)d_in[3];   // [512]
    float* out = (float*)d_out;                   // [8,512,64,64]

    __nv_bfloat16* qkvb_p;  cudaGetSymbolAddress((void**)&qkvb_p,  g_qkvb);
    __nv_bfloat16* xb_p;    cudaGetSymbolAddress((void**)&xb_p,    g_xb);
    __nv_bfloat16* midb_p;  cudaGetSymbolAddress((void**)&midb_p,  g_midb);
    __nv_bfloat16* wqkvb_p; cudaGetSymbolAddress((void**)&wqkvb_p, g_wqkvb);
    __nv_bfloat16* woutb_p; cudaGetSymbolAddress((void**)&woutb_p, g_woutb);

    static int attr_set = 0;
    if (!attr_set) {
        cudaFuncSetAttribute(gemm_bf16_pipe,
                             cudaFuncAttributeMaxDynamicSharedMemorySize,
                             GEMM_SMEM_BYTES);
        cudaFuncSetAttribute(fused_proj_ln,
                             cudaFuncAttributeMaxDynamicSharedMemorySize,
                             FUSED_SMEM_BYTES);
        cudaFuncSetAttribute(apply_kernel,
                             cudaFuncAttributeMaxDynamicSharedMemorySize,
                             APPLY_SMEM_BYTES);
        attr_set = 1;
    }

    // bf16 conversions
    {
        int nx = BATCH * CIN * NPIX;
        cvt_bf16_kernel<<<nx / 4 / 256, 256>>>(x, xb_p, nx);
        int nw1 = OCQKV * CIN;
        cvt_bf16_kernel<<<nw1 / 4 / 256, 256>>>(w_qkv, wqkvb_p, nw1);
        int nw2 = INNER * INNER;
        cvt_bf16_kernel<<<nw2 / 4 / 256, 256>>>(w_out, woutb_p, nw2);
    }
    zero_ctx_kernel<<<(BATCH * HEADS * DH * DH + 255) / 256, 256>>>();

    // qkv = w_qkv @ x  : M=1536, K=512, N=4096 per batch  (bf16 out)
    gemm_bf16_pipe<<<dim3(NPIX / BN, OCQKV / BM, BATCH), 256, GEMM_SMEM_BYTES>>>(
        wqkvb_p, xb_p, qkvb_p, OCQKV, CIN, NPIX);
    softmax_k_kernel<<<BATCH * INNER, 256>>>();
    context_kernel<<<dim3(8, HEADS, BATCH), 256>>>();
    apply_kernel<<<dim3(NPIX / 256, HEADS, BATCH), 256, APPLY_SMEM_BYTES>>>();
    // fused: out = LN(w_out @ mid + b_out)
    fused_proj_ln<<<dim3(NPIX / FBN, 1, BATCH), 512, FUSED_SMEM_BYTES>>>(
        woutb_p, midb_p, out, b_out);
}

// round 17
// speedup vs baseline: 1.2510x; 1.2510x over previous
#include <cuda_runtime.h>
#include <cuda_bf16.h>
#include <math_constants.h>
#include <cstdint>

// Problem constants
#define BATCH 8
#define CIN   512
#define NPIX  4096          // 64*64
#define OCQKV 1536          // 3 * INNER
#define INNER 512
#define HEADS 8
#define DH    64
#define INV_N (1.0f/4096.0f)

// GEMM1 tiling: CTA 128x128, BK=32, bf16 m16n8k16, 4-stage cp.async ring
#define BM 128
#define BN 128
#define BK 32
#define AS2 40              // A smem row stride (bf16)
#define BS2 136             // B smem row stride (bf16)
#define STAGES 4
#define A_STAGE (BM * AS2)  // 5120 elems
#define B_STAGE (BK * BS2)  // 4352 elems
#define GEMM_SMEM_BYTES (STAGES * (A_STAGE + B_STAGE) * 2)   // 75776
#define APPLY_SMEM_BYTES (DH * 256 * 2 + DH * DH * 4)        // 49152

// Fused proj+LN tiling: CTA 512x64 (full channel dim), 512 threads
#define FBM 512
#define FBN 64
#define FAS 40              // A row stride (k-major)
#define FBS2 40             // B row stride: 32 k + 8 pad (mid is [n][k])
#define FA_STAGE (FBM * FAS)    // 20480 elems
#define FB_STAGE2 (FBN * FBS2)  // 2560 elems
#define FUSED_SMEM_BYTES (STAGES * (FA_STAGE + FB_STAGE2) * 2)  // 184320

// Scratch (allocation-free: __device__ globals)
__device__ __align__(16) __nv_bfloat16 g_qkvb[(size_t)BATCH * OCQKV * NPIX]; // 96 MB
__device__ __align__(16) float g_ctx [(size_t)BATCH * HEADS * DH * DH];       // 1 MB
__device__ __align__(16) __nv_bfloat16 g_xb  [(size_t)BATCH * CIN * NPIX];    // 32 MB
// mid stored PIXEL-MAJOR: [b][pix][ch] -> apply stores coalesced, fused reads [n][k]
__device__ __align__(16) __nv_bfloat16 g_midb[(size_t)BATCH * NPIX * INNER];  // 32 MB
__device__ __align__(16) __nv_bfloat16 g_wqkvb[(size_t)OCQKV * CIN];          // 1.5 MB [M,K]
__device__ __align__(16) __nv_bfloat16 g_woutb[(size_t)INNER * INNER];        // 0.5 MB [M,K]

// ---------------------------------------------------------------------------
__device__ __forceinline__ void cp_async16(void* smem, const void* gmem) {
    uint32_t s = (uint32_t)__cvta_generic_to_shared(smem);
    asm volatile("cp.async.cg.shared.global [%0], [%1], 16;" :: "r"(s), "l"(gmem));
}

__device__ __forceinline__ uint32_t smem_u32(const void* p) {
    return (uint32_t)__cvta_generic_to_shared(p);
}

__device__ __forceinline__ void ldmx4(uint32_t* r, uint32_t addr) {
    asm volatile("ldmatrix.sync.aligned.m8n8.x4.shared.b16 {%0,%1,%2,%3}, [%4];"
                 : "=r"(r[0]), "=r"(r[1]), "=r"(r[2]), "=r"(r[3]) : "r"(addr));
}

__device__ __forceinline__ void ldmx4_trans(uint32_t* r, uint32_t addr) {
    asm volatile("ldmatrix.sync.aligned.m8n8.x4.trans.shared.b16 {%0,%1,%2,%3}, [%4];"
                 : "=r"(r[0]), "=r"(r[1]), "=r"(r[2]), "=r"(r[3]) : "r"(addr));
}

__device__ __forceinline__ void mma_bf16(float* c, const uint32_t* a, const uint32_t* b) {
    asm volatile(
        "mma.sync.aligned.m16n8k16.row.col.f32.bf16.bf16.f32 "
        "{%0,%1,%2,%3}, {%4,%5,%6,%7}, {%8,%9}, {%0,%1,%2,%3};\n"
        : "+f"(c[0]), "+f"(c[1]), "+f"(c[2]), "+f"(c[3])
        : "r"(a[0]), "r"(a[1]), "r"(a[2]), "r"(a[3]), "r"(b[0]), "r"(b[1]));
}

// ---------------------------------------------------------------------------
// fp32 -> bf16 convert (vectorized x4)
// ---------------------------------------------------------------------------
__global__ __launch_bounds__(256) void cvt_bf16_kernel(
    const float* __restrict__ in, __nv_bfloat16* __restrict__ out, int n)
{
    int i = (blockIdx.x * 256 + threadIdx.x) * 4;
    if (i < n) {
        float4 v = *reinterpret_cast<const float4*>(in + i);
        __nv_bfloat162 lo = __floats2bfloat162_rn(v.x, v.y);
        __nv_bfloat162 hi = __floats2bfloat162_rn(v.z, v.w);
        uint2 pk;
        pk.x = *reinterpret_cast<uint32_t*>(&lo);
        pk.y = *reinterpret_cast<uint32_t*>(&hi);
        *reinterpret_cast<uint2*>(out + i) = pk;
    }
}

// ---------------------------------------------------------------------------
// GEMM1: 4-stage pipelined bf16, bf16 out. CTA 128x128 (8 warps 4Mx2N).
// 2 CTAs/SM (natural ~96 regs, NO cap — round-16 showed the 3-CTA reg cap
// spills the mainloop and regresses 30%).
// ---------------------------------------------------------------------------
__global__ __launch_bounds__(256, 2) void gemm_bf16_pipe(
    const __nv_bfloat16* __restrict__ A,   // [M,K]
    const __nv_bfloat16* __restrict__ Xg,  // [BATCH][K][N]
    __nv_bfloat16* __restrict__ Yg,        // [BATCH][M][N]
    int M, int K, int Nn)
{
    extern __shared__ __nv_bfloat16 smb[];
    __nv_bfloat16* Asm = smb;
    __nv_bfloat16* Bsm = smb + STAGES * A_STAGE;

    const int b  = blockIdx.z;
    const __nv_bfloat16* X = Xg + (size_t)b * K * Nn;
    __nv_bfloat16* Y = Yg + (size_t)b * M * Nn;
    const int m0 = blockIdx.y * BM;
    const int n0 = blockIdx.x * BN;
    const int tid  = threadIdx.x;
    const int lane = tid & 31;
    const int warp = tid >> 5;
    const int wm = (warp & 3) * 32;
    const int wn = (warp >> 2) * 64;
    const int r = lane >> 2;
    const int c = lane & 3;

    const int NIT = K >> 5;

    float acc[2][8][4];
#pragma unroll
    for (int mt = 0; mt < 2; mt++)
#pragma unroll
        for (int nt = 0; nt < 8; nt++)
#pragma unroll
            for (int i = 0; i < 4; i++) acc[mt][nt][i] = 0.f;

    auto load_stage = [&](int s, int k0) {
        const __nv_bfloat16* a_src = A + (size_t)m0 * K + k0;
        const __nv_bfloat16* b_src = X + (size_t)k0 * Nn + n0;
        __nv_bfloat16* Ad = Asm + s * A_STAGE;
        __nv_bfloat16* Bd = Bsm + s * B_STAGE;
#pragma unroll
        for (int u = 0; u < 2; u++) {
            int idx = tid + u * 256;
            int m  = idx >> 2, ga = idx & 3;
            cp_async16(&Ad[m * AS2 + ga * 8], a_src + (size_t)m * K + ga * 8);
            int kk = idx >> 4, gb = idx & 15;
            cp_async16(&Bd[kk * BS2 + gb * 8], b_src + (size_t)kk * Nn + gb * 8);
        }
    };

    const int lane15 = lane & 15;
    const int khalf  = (lane >> 4) << 3;
    const uint32_t a_base = smem_u32(Asm) + (uint32_t)((wm + lane15) * AS2 + khalf) * 2;
    const uint32_t b_base = smem_u32(Bsm) + (uint32_t)(lane15 * BS2 + wn + khalf) * 2;

    load_stage(0, 0);       asm volatile("cp.async.commit_group;");
    load_stage(1, BK);      asm volatile("cp.async.commit_group;");
    load_stage(2, 2 * BK);  asm volatile("cp.async.commit_group;");

    for (int it = 0; it < NIT; it++) {
        asm volatile("cp.async.wait_group 2;");
        __syncthreads();

        if (it + 3 < NIT)
            load_stage((it + 3) & 3, (it + 3) * BK);
        asm volatile("cp.async.commit_group;");

        const uint32_t aoff = a_base + (uint32_t)((it & 3) * A_STAGE) * 2;
        const uint32_t boff = b_base + (uint32_t)((it & 3) * B_STAGE) * 2;

#pragma unroll
        for (int ks = 0; ks < 2; ks++) {
            const int kc = ks * 16;
            uint32_t af[2][4];
            ldmx4(af[0], aoff + kc * 2);
            ldmx4(af[1], aoff + (16 * AS2 + kc) * 2);
#pragma unroll
            for (int j = 0; j < 4; j++) {
                uint32_t bf[4];
                ldmx4_trans(bf, boff + (kc * BS2 + j * 16) * 2);
                mma_bf16(acc[0][2 * j],     af[0], bf);
                mma_bf16(acc[0][2 * j + 1], af[0], bf + 2);
                mma_bf16(acc[1][2 * j],     af[1], bf);
                mma_bf16(acc[1][2 * j + 1], af[1], bf + 2);
            }
        }
    }

#pragma unroll
    for (int mt = 0; mt < 2; mt++) {
        const int mrow = m0 + wm + mt * 16 + r;
#pragma unroll
        for (int nt = 0; nt < 8; nt++) {
            const int ncol = n0 + wn + nt * 8 + 2 * c;
            __nv_bfloat162 o0 = __floats2bfloat162_rn(acc[mt][nt][0], acc[mt][nt][1]);
            __nv_bfloat162 o1 = __floats2bfloat162_rn(acc[mt][nt][2], acc[mt][nt][3]);
            *reinterpret_cast<__nv_bfloat162*>(&Y[(size_t)mrow * Nn + ncol]) = o0;
            *reinterpret_cast<__nv_bfloat162*>(&Y[(size_t)(mrow + 8) * Nn + ncol]) = o1;
        }
    }
}

// ---------------------------------------------------------------------------
// FUSED proj GEMM + channel LayerNorm.
// CTA 512(M) x 64(N px), 512 threads / 16 warps along M, warp tile 32x64.
// mid is PIXEL-MAJOR [b][n][k]: B tile rows = pixels, ldmatrix NON-trans.
// ---------------------------------------------------------------------------
__global__ __launch_bounds__(512, 1) void fused_proj_ln(
    const __nv_bfloat16* __restrict__ A,   // [512, 512] bf16 [M,K]
    const __nv_bfloat16* __restrict__ Mg,  // [BATCH][NPIX][512] bf16 (pixel-major)
    float* __restrict__ out,               // [BATCH][512][NPIX]
    const float* __restrict__ bias)
{
    extern __shared__ __nv_bfloat16 smb[];
    __nv_bfloat16* Asm = smb;                          // [STAGES][512][FAS]
    __nv_bfloat16* Bsm = smb + STAGES * FA_STAGE;      // [STAGES][FBN][FBS2]

    const int b  = blockIdx.z;
    const __nv_bfloat16* X = Mg + (size_t)b * NPIX * INNER;
    const int n0 = blockIdx.x * FBN;
    const int tid  = threadIdx.x;
    const int lane = tid & 31;
    const int warp = tid >> 5;          // 0..15
    const int wm = warp * 32;
    const int r = lane >> 2;            // 0..7
    const int c = lane & 3;             // 0..3

    const int NIT = INNER >> 5;         // 16

    float acc[2][8][4];
#pragma unroll
    for (int mt = 0; mt < 2; mt++)
#pragma unroll
        for (int nt = 0; nt < 8; nt++)
#pragma unroll
            for (int i = 0; i < 4; i++) acc[mt][nt][i] = 0.f;

    auto load_stage = [&](int s, int k0) {
        const __nv_bfloat16* a_src = A + k0;
        const __nv_bfloat16* b_src = X + (size_t)n0 * INNER + k0;
        __nv_bfloat16* Ad = Asm + s * FA_STAGE;
        __nv_bfloat16* Bd = Bsm + s * FB_STAGE2;
#pragma unroll
        for (int u = 0; u < 4; u++) {
            int idx = tid + u * 512;          // 2048 chunks: 512 rows x 4
            int m  = idx >> 2, ga = idx & 3;
            cp_async16(&Ad[m * FAS + ga * 8], a_src + (size_t)m * INNER + ga * 8);
        }
        if (tid < 256) {                      // 256 chunks: 64 n-rows x 4
            int row = tid >> 2, gb = tid & 3;
            cp_async16(&Bd[row * FBS2 + gb * 8], b_src + (size_t)row * INNER + gb * 8);
        }
    };

    const int lane15 = lane & 15;
    const int khalf  = (lane >> 4) << 3;
    const uint32_t a_base = smem_u32(Asm) + (uint32_t)((wm + lane15) * FAS + khalf) * 2;
    const uint32_t b_base = smem_u32(Bsm) + (uint32_t)(lane15 * FBS2 + khalf) * 2;

    load_stage(0, 0);       asm volatile("cp.async.commit_group;");
    load_stage(1, BK);      asm volatile("cp.async.commit_group;");
    load_stage(2, 2 * BK);  asm volatile("cp.async.commit_group;");

    for (int it = 0; it < NIT; it++) {
        asm volatile("cp.async.wait_group 2;");
        __syncthreads();

        if (it + 3 < NIT)
            load_stage((it + 3) & 3, (it + 3) * BK);
        asm volatile("cp.async.commit_group;");

        const uint32_t aoff = a_base + (uint32_t)((it & 3) * FA_STAGE) * 2;
        const uint32_t boff = b_base + (uint32_t)((it & 3) * FB_STAGE2) * 2;

#pragma unroll
        for (int ks = 0; ks < 2; ks++) {
            const int kc = ks * 16;
            uint32_t af[2][4];
            ldmx4(af[0], aoff + kc * 2);
            ldmx4(af[1], aoff + (16 * FAS + kc) * 2);
#pragma unroll
            for (int j = 0; j < 4; j++) {
                uint32_t bq[4];
                ldmx4(bq, boff + (j * 16 * FBS2 + kc) * 2);
                uint32_t blo[2] = { bq[0], bq[2] };   // n-lo (rows j*16+0..7)
                uint32_t bhi[2] = { bq[1], bq[3] };   // n-hi (rows j*16+8..15)
                mma_bf16(acc[0][2 * j],     af[0], blo);
                mma_bf16(acc[0][2 * j + 1], af[0], bhi);
                mma_bf16(acc[1][2 * j],     af[1], blo);
                mma_bf16(acc[1][2 * j + 1], af[1], bhi);
            }
        }
    }

    asm volatile("cp.async.wait_group 0;");
    __syncthreads();   // stage smem dead; reuse for LN stats below

    // --- bias ---
#pragma unroll
    for (int mt = 0; mt < 2; mt++) {
        const float bv0 = bias[wm + mt * 16 + r];
        const float bv1 = bias[wm + mt * 16 + r + 8];
#pragma unroll
        for (int nt = 0; nt < 8; nt++) {
            acc[mt][nt][0] += bv0; acc[mt][nt][1] += bv0;
            acc[mt][nt][2] += bv1; acc[mt][nt][3] += bv1;
        }
    }

    // --- per-column partial sums ---
    float se[8], so[8], qe[8], qo[8];
#pragma unroll
    for (int nt = 0; nt < 8; nt++) {
        se[nt] = acc[0][nt][0] + acc[0][nt][2] + acc[1][nt][0] + acc[1][nt][2];
        so[nt] = acc[0][nt][1] + acc[0][nt][3] + acc[1][nt][1] + acc[1][nt][3];
        qe[nt] = acc[0][nt][0]*acc[0][nt][0] + acc[0][nt][2]*acc[0][nt][2]
               + acc[1][nt][0]*acc[1][nt][0] + acc[1][nt][2]*acc[1][nt][2];
        qo[nt] = acc[0][nt][1]*acc[0][nt][1] + acc[0][nt][3]*acc[0][nt][3]
               + acc[1][nt][1]*acc[1][nt][1] + acc[1][nt][3]*acc[1][nt][3];
    }
#pragma unroll
    for (int off = 4; off <= 16; off <<= 1) {
#pragma unroll
        for (int nt = 0; nt < 8; nt++) {
            se[nt] += __shfl_xor_sync(0xffffffff, se[nt], off);
            so[nt] += __shfl_xor_sync(0xffffffff, so[nt], off);
            qe[nt] += __shfl_xor_sync(0xffffffff, qe[nt], off);
            qo[nt] += __shfl_xor_sync(0xffffffff, qo[nt], off);
        }
    }

    float* ssum  = reinterpret_cast<float*>(smb);            // [16][64]
    float* ssum2 = ssum + 16 * 64;                           // [16][64]
    float* smu   = ssum2 + 16 * 64;                          // [64]
    float* srs   = smu + 64;                                 // [64]

    if (lane < 4) {
#pragma unroll
        for (int nt = 0; nt < 8; nt++) {
            ssum [warp * 64 + nt * 8 + 2 * lane]     = se[nt];
            ssum [warp * 64 + nt * 8 + 2 * lane + 1] = so[nt];
            ssum2[warp * 64 + nt * 8 + 2 * lane]     = qe[nt];
            ssum2[warp * 64 + nt * 8 + 2 * lane + 1] = qo[nt];
        }
    }
    __syncthreads();

    if (tid < 64) {
        float ts = 0.f, ts2 = 0.f;
#pragma unroll
        for (int w = 0; w < 16; w++) {
            ts  += ssum [w * 64 + tid];
            ts2 += ssum2[w * 64 + tid];
        }
        const float mu  = ts * (1.f / 512.f);
        const float var = ts2 * (1.f / 512.f) - mu * mu;
        smu[tid] = mu;
        srs[tid] = rsqrtf(var + 1e-5f);
    }
    __syncthreads();

    // --- normalize + store ---
    float* ob = out + (size_t)b * INNER * NPIX;
#pragma unroll
    for (int nt = 0; nt < 8; nt++) {
        const int col = nt * 8 + 2 * c;
        const float mu0 = smu[col],     rs0 = srs[col];
        const float mu1 = smu[col + 1], rs1 = srs[col + 1];
#pragma unroll
        for (int mt = 0; mt < 2; mt++) {
            const int mrow = wm + mt * 16 + r;
            float2 o0, o1;
            o0.x = (acc[mt][nt][0] - mu0) * rs0;
            o0.y = (acc[mt][nt][1] - mu1) * rs1;
            o1.x = (acc[mt][nt][2] - mu0) * rs0;
            o1.y = (acc[mt][nt][3] - mu1) * rs1;
            *reinterpret_cast<float2*>(&ob[(size_t)mrow * NPIX + n0 + col]) = o0;
            *reinterpret_cast<float2*>(&ob[(size_t)(mrow + 8) * NPIX + n0 + col]) = o1;
        }
    }
}

// ---------------------------------------------------------------------------
// softmax over N (4096 bf16 contiguous) for the k block. One block per row.
// ---------------------------------------------------------------------------
__global__ __launch_bounds__(256) void softmax_k_kernel()
{
    const int row = blockIdx.x;
    const int b   = row >> 9;
    const int ch  = row & 511;
    __nv_bfloat16* base = g_qkvb + ((size_t)b * OCQKV + INNER + ch) * NPIX;
    const int tid = threadIdx.x;
    const int lane = tid & 31, wid = tid >> 5;

    __shared__ float red[8];
    __shared__ float bcast;

    uint32_t w[8];
    *reinterpret_cast<uint4*>(w)     = *reinterpret_cast<const uint4*>(base + tid * 16);
    *reinterpret_cast<uint4*>(w + 4) = *reinterpret_cast<const uint4*>(base + tid * 16 + 8);
    float vals[16];
#pragma unroll
    for (int i = 0; i < 8; i++) {
        float2 f = __bfloat1622float2(*reinterpret_cast<__nv_bfloat162*>(&w[i]));
        vals[2 * i] = f.x; vals[2 * i + 1] = f.y;
    }

    float m = vals[0];
#pragma unroll
    for (int j = 1; j < 16; j++) m = fmaxf(m, vals[j]);
#pragma unroll
    for (int off = 16; off > 0; off >>= 1)
        m = fmaxf(m, __shfl_xor_sync(0xffffffff, m, off));
    if (lane == 0) red[wid] = m;
    __syncthreads();
    if (tid == 0) {
        float mm = red[0];
#pragma unroll
        for (int w2 = 1; w2 < 8; w2++) mm = fmaxf(mm, red[w2]);
        bcast = mm;
    }
    __syncthreads();
    const float mx = bcast;

    float s = 0.f;
#pragma unroll
    for (int j = 0; j < 16; j++) { vals[j] = __expf(vals[j] - mx); s += vals[j]; }
#pragma unroll
    for (int off = 16; off > 0; off >>= 1)
        s += __shfl_xor_sync(0xffffffff, s, off);
    if (lane == 0) red[wid] = s;
    __syncthreads();
    if (tid == 0) {
        float ss = 0.f;
#pragma unroll
        for (int w2 = 0; w2 < 8; w2++) ss += red[w2];
        bcast = 1.f / ss;
    }
    __syncthreads();
    const float inv = bcast;
#pragma unroll
    for (int i = 0; i < 8; i++) {
        __nv_bfloat162 o = __floats2bfloat162_rn(vals[2 * i] * inv, vals[2 * i + 1] * inv);
        w[i] = *reinterpret_cast<uint32_t*>(&o);
    }
    *reinterpret_cast<uint4*>(base + tid * 16)     = *reinterpret_cast<uint4*>(w);
    *reinterpret_cast<uint4*>(base + tid * 16 + 8) = *reinterpret_cast<uint4*>(w + 4);
}

__global__ __launch_bounds__(256) void zero_ctx_kernel()
{
    int i = blockIdx.x * 256 + threadIdx.x;
    if (i < BATCH * HEADS * DH * DH) g_ctx[i] = 0.f;
}

// ---------------------------------------------------------------------------
// context[b,h,d,e] += sum_{n in chunk} k_sm[d,n] * (v[e,n]/N)   (bf16 reads)
// ---------------------------------------------------------------------------
__global__ __launch_bounds__(256) void context_kernel()
{
    const int nchunk = blockIdx.x;
    const int h = blockIdx.y;
    const int b = blockIdx.z;
    const __nv_bfloat16* kbase = g_qkvb + ((size_t)b * OCQKV + INNER     + h * DH) * NPIX;
    const __nv_bfloat16* vbase = g_qkvb + ((size_t)b * OCQKV + 2 * INNER + h * DH) * NPIX;

    __shared__ float Ks[64][65];
    __shared__ float Vs[64][65];

    const int tid = threadIdx.x;
    const int ty = tid >> 4, tx = tid & 15;
    float acc[4][4];
#pragma unroll
    for (int i = 0; i < 4; i++)
#pragma unroll
        for (int j = 0; j < 4; j++) acc[i][j] = 0.f;

    for (int nt = 0; nt < 8; nt++) {
        const int n0 = nchunk * 512 + nt * 64;
#pragma unroll
        for (int it = 0; it < 2; it++) {
            int idx = tid + it * 256;
            int r  = idx >> 3;
            int c8 = (idx & 7) * 8;
            uint4 kv = *reinterpret_cast<const uint4*>(&kbase[(size_t)r * NPIX + n0 + c8]);
            uint4 vv = *reinterpret_cast<const uint4*>(&vbase[(size_t)r * NPIX + n0 + c8]);
            const uint32_t* kw = reinterpret_cast<const uint32_t*>(&kv);
            const uint32_t* vw = reinterpret_cast<const uint32_t*>(&vv);
#pragma unroll
            for (int q = 0; q < 4; q++) {
                float2 kf = __bfloat1622float2(*reinterpret_cast<const __nv_bfloat162*>(&kw[q]));
                float2 vf = __bfloat1622float2(*reinterpret_cast<const __nv_bfloat162*>(&vw[q]));
                Ks[c8 + 2 * q][r]     = kf.x;
                Ks[c8 + 2 * q + 1][r] = kf.y;
                Vs[c8 + 2 * q][r]     = vf.x * INV_N;
                Vs[c8 + 2 * q + 1][r] = vf.y * INV_N;
            }
        }
        __syncthreads();
#pragma unroll
        for (int nn = 0; nn < 64; nn++) {
            float kr[4], vr[4];
#pragma unroll
            for (int i = 0; i < 4; i++) kr[i] = Ks[nn][ty * 4 + i];
#pragma unroll
            for (int j = 0; j < 4; j++) vr[j] = Vs[nn][tx * 4 + j];
#pragma unroll
            for (int i = 0; i < 4; i++)
#pragma unroll
                for (int j = 0; j < 4; j++) acc[i][j] += kr[i] * vr[j];
        }
        __syncthreads();
    }
    float* cbase = g_ctx + (size_t)(b * HEADS + h) * DH * DH;
#pragma unroll
    for (int i = 0; i < 4; i++)
#pragma unroll
        for (int j = 0; j < 4; j++)
            atomicAdd(&cbase[(ty * 4 + i) * DH + tx * 4 + j], acc[i][j]);
}

// ---------------------------------------------------------------------------
// Fused softmax_q + apply, q tile staged in smem (single global read).
// Writes g_midb PIXEL-MAJOR: [b][n][h*64+e] -> 8x uint4 contiguous per thread.
// ---------------------------------------------------------------------------
__global__ __launch_bounds__(256) void apply_kernel()
{
    extern __shared__ char ap_sm[];
    __nv_bfloat16* sq = reinterpret_cast<__nv_bfloat16*>(ap_sm);      // [64][256]
    float* ctxs = reinterpret_cast<float*>(ap_sm + DH * 256 * 2);     // [64][64]

    const int n0 = blockIdx.x * 256;
    const int h = blockIdx.y;
    const int b = blockIdx.z;
    const int tid = threadIdx.x;

    const float* csrc = g_ctx + (size_t)(b * HEADS + h) * DH * DH;
    for (int i = tid; i < DH * DH; i += 256)
        ctxs[i] = csrc[i];

    const __nv_bfloat16* qb = g_qkvb + ((size_t)b * OCQKV + h * DH) * NPIX + n0;
#pragma unroll
    for (int u = 0; u < 8; u++) {
        int idx = tid + u * 256;
        int d  = idx >> 5;
        int c8 = (idx & 31) * 8;
        *reinterpret_cast<uint4*>(&sq[d * 256 + c8]) =
            *reinterpret_cast<const uint4*>(qb + (size_t)d * NPIX + c8);
    }
    __syncthreads();

    const int p = tid;
    float mx = -CUDART_INF_F;
#pragma unroll 8
    for (int d = 0; d < 64; d++)
        mx = fmaxf(mx, __bfloat162float(sq[d * 256 + p]));
    float s = 0.f;
#pragma unroll 8
    for (int d = 0; d < 64; d++)
        s += __expf(__bfloat162float(sq[d * 256 + p]) - mx);
    const float inv = 1.f / (s * 8.f);

    float acc[64];
#pragma unroll
    for (int e = 0; e < 64; e++) acc[e] = 0.f;
#pragma unroll 4
    for (int d = 0; d < 64; d++) {
        float qd = __expf(__bfloat162float(sq[d * 256 + p]) - mx) * inv;
        const float* cr = &ctxs[d * 64];
#pragma unroll
        for (int e = 0; e < 64; e++) acc[e] += cr[e] * qd;
    }
    // pixel-major coalesced store: 64 contiguous bf16 per thread
    __nv_bfloat16* obase = g_midb + ((size_t)b * NPIX + n0 + p) * INNER + h * DH;
#pragma unroll
    for (int e = 0; e < 64; e += 8) {
        uint4 pk;
        uint32_t* pw = reinterpret_cast<uint32_t*>(&pk);
#pragma unroll
        for (int q = 0; q < 4; q++) {
            __nv_bfloat162 o = __floats2bfloat162_rn(acc[e + 2 * q], acc[e + 2 * q + 1]);
            pw[q] = *reinterpret_cast<uint32_t*>(&o);
        }
        *reinterpret_cast<uint4*>(obase + e) = pk;
    }
}

// ---------------------------------------------------------------------------
extern "C" void kernel_launch(void* const* d_in, const int* in_sizes, int n_in,
                              void* d_out, int out_size)
{
    (void)in_sizes; (void)n_in; (void)out_size;
    const float* x     = (const float*)d_in[0];   // [8,512,64,64]
    const float* w_qkv = (const float*)d_in[1];   // [1536,512]
    const float* w_out = (const float*)d_in[2];   // [512,512]
    const float* b_out = (const float*)d_in[3];   // [512]
    float* out = (float*)d_out;                   // [8,512,64,64]

    __nv_bfloat16* qkvb_p;  cudaGetSymbolAddress((void**)&qkvb_p,  g_qkvb);
    __nv_bfloat16* xb_p;    cudaGetSymbolAddress((void**)&xb_p,    g_xb);
    __nv_bfloat16* midb_p;  cudaGetSymbolAddress((void**)&midb_p,  g_midb);
    __nv_bfloat16* wqkvb_p; cudaGetSymbolAddress((void**)&wqkvb_p, g_wqkvb);
    __nv_bfloat16* woutb_p; cudaGetSymbolAddress((void**)&woutb_p, g_woutb);

    static int attr_set = 0;
    if (!attr_set) {
        cudaFuncSetAttribute(gemm_bf16_pipe,
                             cudaFuncAttributeMaxDynamicSharedMemorySize,
                             GEMM_SMEM_BYTES);
        cudaFuncSetAttribute(fused_proj_ln,
                             cudaFuncAttributeMaxDynamicSharedMemorySize,
                             FUSED_SMEM_BYTES);
        cudaFuncSetAttribute(apply_kernel,
                             cudaFuncAttributeMaxDynamicSharedMemorySize,
                             APPLY_SMEM_BYTES);
        attr_set = 1;
    }

    // bf16 conversions
    {
        int nx = BATCH * CIN * NPIX;
        cvt_bf16_kernel<<<nx / 4 / 256, 256>>>(x, xb_p, nx);
        int nw1 = OCQKV * CIN;
        cvt_bf16_kernel<<<nw1 / 4 / 256, 256>>>(w_qkv, wqkvb_p, nw1);
        int nw2 = INNER * INNER;
        cvt_bf16_kernel<<<nw2 / 4 / 256, 256>>>(w_out, woutb_p, nw2);
    }
    zero_ctx_kernel<<<(BATCH * HEADS * DH * DH + 255) / 256, 256>>>();

    // qkv = w_qkv @ x  : M=1536, K=512, N=4096 per batch  (bf16 out)
    gemm_bf16_pipe<<<dim3(NPIX / BN, OCQKV / BM, BATCH), 256, GEMM_SMEM_BYTES>>>(
        wqkvb_p, xb_p, qkvb_p, OCQKV, CIN, NPIX);
    softmax_k_kernel<<<BATCH * INNER, 256>>>();
    context_kernel<<<dim3(8, HEADS, BATCH), 256>>>();
    apply_kernel<<<dim3(NPIX / 256, HEADS, BATCH), 256, APPLY_SMEM_BYTES>>>();
    // fused: out = LN(w_out @ mid + b_out)
    fused_proj_ln<<<dim3(NPIX / FBN, 1, BATCH), 512, FUSED_SMEM_BYTES>>>(
        woutb_p, midb_p, out, b_out);
}